// round 14
// baseline (speedup 1.0000x reference)
#include <cuda_runtime.h>
#include <cuda_fp16.h>
#include <cstdint>

#define L_LAYERS 6
#define DIMV     40
#define HV       128
#define ADIMV    20
#define BTOT     131072
#define MTILE    64
#define NTHR     256
#define ZASTR    28

// fp16 packed weight segments per layer (uint32 words)
#define OC  0         // W1 ctx rows 20..147 : 8 ks16 x 8 ntp x 32 x 4
#define OT  8192      // W1 te  rows 148..275
#define O2  16384     // W2
#define O3  24576     // W3
#define O4  32768     // [Ws|Wt|0] : 8 ks16 x 6 nt x 32 x 2
#define WPH_L 35840
// tf32 za weights per layer (floats): 3 ks8 x 8 ntp x 32 x 4
#define WPA_L 3072

__device__ unsigned g_wph[6 * WPH_L];
__device__ float    g_wpa[6 * WPA_L];
__device__ unsigned g_apk[2 * (size_t)BTOT * 64];   // ctx|te fp16 A-frag order

// smem word offsets
#define SM_HF   0                 // h frag: 4 rb16 x 8 kb x 4 comp x 32 lane = 4096
#define SM_ST   4096              // st 64x41 fp32 = 2624
#define SM_Z    6720              // z 64x40 = 2560
#define SM_ZA   9280              // za 64x28 = 1792
#define SM_ZB   11072             // zb 64x20 = 1280
#define SM_IDX  12352             // 4 x 120 ints
#define SM_WORDS 12832
#define SMEM_BYTES (SM_WORDS * 4)

__device__ __forceinline__ unsigned f2tf(float x) {
    unsigned r;
    asm("cvt.rna.tf32.f32 %0, %1;" : "=r"(r) : "f"(x));
    return r;
}
__device__ __forceinline__ unsigned h2pack(float a, float b) {
    __half2 h = __floats2half2_rn(a, b);
    return *reinterpret_cast<unsigned*>(&h);
}
__device__ __forceinline__ void mma8(float c[4], const unsigned a[4], const unsigned b[2]) {
    asm volatile(
        "mma.sync.aligned.m16n8k8.row.col.f32.tf32.tf32.f32 "
        "{%0,%1,%2,%3}, {%4,%5,%6,%7}, {%8,%9}, {%0,%1,%2,%3};\n"
        : "+f"(c[0]), "+f"(c[1]), "+f"(c[2]), "+f"(c[3])
        : "r"(a[0]), "r"(a[1]), "r"(a[2]), "r"(a[3]), "r"(b[0]), "r"(b[1]));
}
__device__ __forceinline__ void mma16(float c[4], const unsigned a[4], unsigned b0, unsigned b1) {
    asm volatile(
        "mma.sync.aligned.m16n8k16.row.col.f32.f16.f16.f32 "
        "{%0,%1,%2,%3}, {%4,%5,%6,%7}, {%8,%9}, {%0,%1,%2,%3};\n"
        : "+f"(c[0]), "+f"(c[1]), "+f"(c[2]), "+f"(c[3])
        : "r"(a[0]), "r"(a[1]), "r"(a[2]), "r"(a[3]), "r"(b0), "r"(b1));
}
// silu via tanh.approx: silu(v) = t + t*tanh(t), t = v/2   (1 MUFU instead of 2)
__device__ __forceinline__ float silu(float v) {
    float t = 0.5f * v;
    float th;
    asm("tanh.approx.f32 %0, %1;" : "=f"(th) : "f"(t));
    return fmaf(t, th, t);
}

// ---------------------------------------------------------------------------
// prep: fp16 weights (frag order) + tf32 za weights
// ---------------------------------------------------------------------------
__global__ void prep_w_kernel(const float* __restrict__ W1, const float* __restrict__ W2,
                              const float* __restrict__ W3, const float* __restrict__ Ws,
                              const float* __restrict__ Wt) {
    int i = blockIdx.x * blockDim.x + threadIdx.x;
    const int FTOT = 6 * WPH_L;
    if (i < FTOT) {
        int layer = i / WPH_L;
        int w = i - layer * WPH_L;
        if (w < O4) {
            int seg = w / 8192;                 // 0:ctx 1:te 2:W2 3:W3
            int idx = w - seg * 8192;
            int comp = idx & 3, lane = (idx >> 2) & 31;
            int ntp = (idx >> 7) & 7, ks = idx >> 10;
            int g = lane >> 2, t4 = lane & 3;
            int col = (ntp * 2 + (comp >> 1)) * 8 + g;
            int k0 = ks * 16 + (comp & 1) * 8 + 2 * t4;
            float v0, v1;
            if (seg == 0) {
                const float* wsrc = W1 + (size_t)layer * 276 * HV;
                v0 = wsrc[(ADIMV + k0) * HV + col]; v1 = wsrc[(ADIMV + k0 + 1) * HV + col];
            } else if (seg == 1) {
                const float* wsrc = W1 + (size_t)layer * 276 * HV;
                v0 = wsrc[(ADIMV + 128 + k0) * HV + col]; v1 = wsrc[(ADIMV + 128 + k0 + 1) * HV + col];
            } else if (seg == 2) {
                const float* wsrc = W2 + (size_t)layer * HV * HV;
                v0 = wsrc[k0 * HV + col]; v1 = wsrc[(k0 + 1) * HV + col];
            } else {
                const float* wsrc = W3 + (size_t)layer * HV * HV;
                v0 = wsrc[k0 * HV + col]; v1 = wsrc[(k0 + 1) * HV + col];
            }
            g_wph[i] = h2pack(v0, v1);
        } else {
            int idx = w - O4;
            int comp = idx & 1, lane = (idx >> 1) & 31;
            int rest = idx >> 6;
            int nt = rest % 6, ks = rest / 6;
            int g = lane >> 2, t4 = lane & 3;
            int col = nt * 8 + g;
            int k0 = ks * 16 + comp * 8 + 2 * t4;
            float v0 = 0.0f, v1 = 0.0f;
            if (col < ADIMV) {
                const float* wsrc = Ws + (size_t)layer * HV * ADIMV;
                v0 = wsrc[k0 * ADIMV + col]; v1 = wsrc[(k0 + 1) * ADIMV + col];
            } else if (col < DIMV) {
                const float* wsrc = Wt + (size_t)layer * HV * ADIMV;
                v0 = wsrc[k0 * ADIMV + col - ADIMV]; v1 = wsrc[(k0 + 1) * ADIMV + col - ADIMV];
            }
            g_wph[i] = h2pack(v0, v1);
        }
        return;
    }
    int j = i - FTOT;
    if (j >= 6 * WPA_L) return;
    int layer = j / WPA_L;
    int idx = j - layer * WPA_L;
    int comp = idx & 3, lane = (idx >> 2) & 31;
    int blk = idx >> 7, ntp = blk & 7, ks = blk >> 3;
    int g = lane >> 2, t4 = lane & 3;
    int row = ks * 8 + t4 + 4 * (comp & 1);
    int col = (ntp * 2 + (comp >> 1)) * 8 + g;
    float v = (row < ADIMV) ? W1[(size_t)layer * 276 * HV + row * HV + col] : 0.0f;
    g_wpa[j] = __uint_as_float(f2tf(v));
}

// ctx/te -> fp16 A-frag order
__global__ void prep_a_kernel(const float* __restrict__ ctx, const float* __restrict__ te) {
    size_t i = (size_t)blockIdx.x * blockDim.x + threadIdx.x;
    const size_t seg_sz = (size_t)BTOT * 64;
    if (i >= 2 * seg_sz) return;
    int seg = (int)(i / seg_sz);
    size_t idx = i - (size_t)seg * seg_sz;
    int comp = (int)(idx & 3);
    int lane = (int)((idx >> 2) & 31);
    int kb = (int)((idx >> 7) & 7);
    size_t rb16 = idx >> 10;
    int g = lane >> 2, t4 = lane & 3;
    size_t row = rb16 * 16 + g + 8 * (comp & 1);
    int kcol = kb * 16 + 8 * (comp >> 1) + 2 * t4;
    const float* src = seg ? te : ctx;
    g_apk[i] = h2pack(src[row * HV + kcol], src[row * HV + kcol + 1]);
}

// ---------------------------------------------------------------------------
// fp16 GEMM pieces: warp tile 16x64, 4wm x 2wn over 64x128
// ---------------------------------------------------------------------------
__device__ __forceinline__ void gemm_h128(float acc[8][4], const unsigned* __restrict__ hw,
                                          const unsigned* __restrict__ Wp,
                                          int wm, int wn, int lane) {
    const uint4* bp = reinterpret_cast<const uint4*>(Wp);
#pragma unroll
    for (int ks = 0; ks < 8; ks++) {
        unsigned a[4];
        const unsigned* ab = hw + ((wm * 8 + ks) * 4) * 32 + lane;
        a[0] = ab[0]; a[1] = ab[32]; a[2] = ab[64]; a[3] = ab[96];
        const uint4* bb = bp + (ks * 8 + wn * 4) * 32 + lane;
#pragma unroll
        for (int ntp = 0; ntp < 4; ntp++) {
            uint4 bv = __ldg(bb + ntp * 32);
            mma16(acc[2 * ntp], a, bv.x, bv.y);
            mma16(acc[2 * ntp + 1], a, bv.z, bv.w);
        }
    }
}

__device__ __forceinline__ void gemm_pk128(float acc[8][4], const unsigned* __restrict__ Apk,
                                           const unsigned* __restrict__ Wp, int rb16,
                                           int wn, int lane) {
    const uint4* ap = reinterpret_cast<const uint4*>(Apk);
    const uint4* bp = reinterpret_cast<const uint4*>(Wp);
#pragma unroll
    for (int ks = 0; ks < 8; ks++) {
        uint4 av = __ldg(ap + ((size_t)rb16 * 8 + ks) * 32 + lane);
        unsigned a[4] = {av.x, av.y, av.z, av.w};
        const uint4* bb = bp + (ks * 8 + wn * 4) * 32 + lane;
#pragma unroll
        for (int ntp = 0; ntp < 4; ntp++) {
            uint4 bv = __ldg(bb + ntp * 32);
            mma16(acc[2 * ntp], a, bv.x, bv.y);
            mma16(acc[2 * ntp + 1], a, bv.z, bv.w);
        }
    }
}

// epilogue: silu+bias -> h frag store (own lane, conflict-free)
__device__ __forceinline__ void epi_silu_h(float acc[8][4], const float* __restrict__ bias,
                                           unsigned* __restrict__ hw,
                                           int wm, int wn, int lane, int t4) {
#pragma unroll
    for (int nt = 0; nt < 8; nt++) {
        int c0 = wn * 64 + nt * 8 + t4 * 2;
        float bb0 = __ldg(bias + c0);
        float bb1 = __ldg(bias + c0 + 1);
        float v0 = silu(acc[nt][0] + bb0);
        float v1 = silu(acc[nt][1] + bb1);
        float v2 = silu(acc[nt][2] + bb0);
        float v3 = silu(acc[nt][3] + bb1);
        int kb = wn * 4 + (nt >> 1);
        int cb = (nt & 1) * 2;
        hw[((wm * 8 + kb) * 4 + cb) * 32 + lane]     = h2pack(v0, v1);
        hw[((wm * 8 + kb) * 4 + cb + 1) * 32 + lane] = h2pack(v2, v3);
    }
}

__device__ __forceinline__ void zacc8(float acc[8][4]) {
#pragma unroll
    for (int nt = 0; nt < 8; nt++)
#pragma unroll
        for (int e = 0; e < 4; e++) acc[nt][e] = 0.0f;
}

// ---------------------------------------------------------------------------
__global__ void __launch_bounds__(NTHR)
flow_fused_kernel(const float* __restrict__ xin, float* __restrict__ zfinal,
                  float* __restrict__ ldfinal,
                  const float* __restrict__ b1, const float* __restrict__ b2,
                  const float* __restrict__ b3, const float* __restrict__ bsw,
                  const float* __restrict__ btw,
                  const int* __restrict__ perm, const int* __restrict__ idxa,
                  const int* __restrict__ idxb) {
    extern __shared__ unsigned smw[];
    unsigned* hw  = smw + SM_HF;
    float* st_s   = (float*)(smw + SM_ST);
    float* z_s    = (float*)(smw + SM_Z);
    float* za_s   = (float*)(smw + SM_ZA);
    float* zb_s   = (float*)(smw + SM_ZB);
    int* sga_all  = (int*)(smw + SM_IDX);
    int* sgb_all  = sga_all + 120;
    int* sia_all  = sgb_all + 120;
    int* sib_all  = sia_all + 120;

    const int tid = threadIdx.x;
    const int warp = tid >> 5, lane = tid & 31;
    const int g = lane >> 2, t4 = lane & 3;
    const int wm = warp >> 1, wn = warp & 1;
    const int rb = blockIdx.x * MTILE;
    const int rb16 = (rb >> 4) + wm;

    if (tid < 120) {
        int l = tid / 20, k = tid - l * 20;
        int v = idxa[l * ADIMV + k];
        sia_all[tid] = v;
        sga_all[tid] = perm[l * DIMV + v];
    } else if (tid < 240) {
        int u = tid - 120;
        int l = u / 20, k = u - l * 20;
        int v = idxb[l * ADIMV + k];
        sib_all[u] = v;
        sgb_all[u] = perm[l * DIMV + v];
    }
    for (int i = tid; i < MTILE * DIMV; i += NTHR)
        z_s[i] = xin[(size_t)rb * DIMV + i];

    float ldacc = 0.0f;

    for (int layer = 0; layer < L_LAYERS; layer++) {
        const unsigned* wl = g_wph + layer * WPH_L;
        const float* wla = g_wpa + layer * WPA_L;
        const int* sga = sga_all + layer * 20;
        const int* sgb = sgb_all + layer * 20;
        const int* sia = sia_all + layer * 20;
        const int* sib = sib_all + layer * 20;

        __syncthreads();
        for (int i = tid; i < MTILE * ADIMV; i += NTHR) {
            int r = i / ADIMV, k = i - r * ADIMV;
            za_s[r * ZASTR + k] = z_s[r * DIMV + sga[k]];
            zb_s[r * ADIMV + k] = z_s[r * DIMV + sgb[k]];
        }
        for (int i = tid; i < MTILE * 4; i += NTHR) {
            int r = i >> 2;
            za_s[r * ZASTR + ADIMV + (i & 3)] = 0.0f;
        }
        __syncthreads();

        float acc[8][4];
        zacc8(acc);

        // GEMM1 seg z_a: tf32 k8 x 3
        {
            const float4* bp = reinterpret_cast<const float4*>(wla);
#pragma unroll
            for (int ks = 0; ks < 3; ks++) {
                const float* ar = za_s + (wm * 16 + g) * ZASTR + ks * 8 + t4;
                unsigned a[4];
                a[0] = f2tf(ar[0]);
                a[1] = f2tf(ar[8 * ZASTR]);
                a[2] = f2tf(ar[4]);
                a[3] = f2tf(ar[8 * ZASTR + 4]);
                const float4* bb = bp + (ks * 8 + wn * 4) * 32 + lane;
#pragma unroll
                for (int ntp = 0; ntp < 4; ntp++) {
                    float4 bv = __ldg(bb + ntp * 32);
                    unsigned b0[2] = {__float_as_uint(bv.x), __float_as_uint(bv.y)};
                    unsigned b1[2] = {__float_as_uint(bv.z), __float_as_uint(bv.w)};
                    mma8(acc[2 * ntp], a, b0);
                    mma8(acc[2 * ntp + 1], a, b1);
                }
            }
        }
        // GEMM1 ctx / te (fp16, prepacked gmem A)
        gemm_pk128(acc, g_apk, wl + OC, rb16, wn, lane);
        gemm_pk128(acc, g_apk + (size_t)BTOT * 64, wl + OT, rb16, wn, lane);
        epi_silu_h(acc, b1 + layer * HV, hw, wm, wn, lane, t4);
        __syncthreads();

        // GEMM2
        zacc8(acc);
        gemm_h128(acc, hw, wl + O2, wm, wn, lane);
        __syncthreads();
        epi_silu_h(acc, b2 + layer * HV, hw, wm, wn, lane, t4);
        __syncthreads();

        // GEMM3
        zacc8(acc);
        gemm_h128(acc, hw, wl + O3, wm, wn, lane);
        __syncthreads();
        epi_silu_h(acc, b3 + layer * HV, hw, wm, wn, lane, t4);
        __syncthreads();

        // GEMM4: N=48, warp tile 16x24
        float a4[3][4];
#pragma unroll
        for (int nt = 0; nt < 3; nt++)
#pragma unroll
            for (int e = 0; e < 4; e++) a4[nt][e] = 0.0f;
        {
            const uint2* bp4 = reinterpret_cast<const uint2*>(wl + O4);
#pragma unroll
            for (int ks = 0; ks < 8; ks++) {
                unsigned a[4];
                const unsigned* ab = hw + ((wm * 8 + ks) * 4) * 32 + lane;
                a[0] = ab[0]; a[1] = ab[32]; a[2] = ab[64]; a[3] = ab[96];
#pragma unroll
                for (int nt = 0; nt < 3; nt++) {
                    uint2 bv = __ldg(bp4 + (ks * 6 + wn * 3 + nt) * 32 + lane);
                    mma16(a4[nt], a, bv.x, bv.y);
                }
            }
        }
        // epilogue4 -> st (fp32)
        {
            const float* bsl = bsw + layer * ADIMV;
            const float* btl = btw + layer * ADIMV;
#pragma unroll
            for (int nt = 0; nt < 3; nt++)
#pragma unroll
                for (int e = 0; e < 4; e++) {
                    int row = wm * 16 + g + ((e >= 2) ? 8 : 0);
                    int col = wn * 24 + nt * 8 + t4 * 2 + (e & 1);
                    if (col < DIMV) {
                        float v = a4[nt][e];
                        if (col < ADIMV) {
                            v += __ldg(bsl + col);
                            v = fminf(fmaxf(v, -2.0f), 2.0f);
                        } else {
                            v += __ldg(btl + col - ADIMV);
                        }
                        st_s[row * 41 + col] = v;
                    }
                }
        }
        __syncthreads();

        // coupling: 4 threads/row
        {
            int r = tid >> 2, q = tid & 3;
            const float* strow = st_s + r * 41;
            float ssum = 0.0f;
#pragma unroll
            for (int j = 0; j < 5; j++) {
                int k = q * 5 + j;
                float s = strow[k];
                float t = strow[ADIMV + k];
                ssum += s;
                float yb = zb_s[r * ADIMV + k] * __expf(s) + t;
                z_s[r * DIMV + sib[k]] = yb;
                z_s[r * DIMV + sia[k]] = za_s[r * ZASTR + k];
            }
            ssum += __shfl_xor_sync(0xffffffffu, ssum, 1);
            ssum += __shfl_xor_sync(0xffffffffu, ssum, 2);
            ldacc += ssum;
        }
        (void)wla;
    }

    __syncthreads();
    for (int i = tid; i < MTILE * DIMV; i += NTHR)
        zfinal[(size_t)rb * DIMV + i] = z_s[i];
    if ((tid & 3) == 0)
        ldfinal[(size_t)rb + (tid >> 2)] = ldacc;
}

extern "C" void kernel_launch(void* const* d_in, const int* in_sizes, int n_in,
                              void* d_out, int out_size) {
    const float* x   = (const float*)d_in[0];
    const float* ctx = (const float*)d_in[1];
    const float* te  = (const float*)d_in[2];
    const float* W1  = (const float*)d_in[3];
    const float* b1  = (const float*)d_in[4];
    const float* W2  = (const float*)d_in[5];
    const float* b2  = (const float*)d_in[6];
    const float* W3  = (const float*)d_in[7];
    const float* b3  = (const float*)d_in[8];
    const float* Ws  = (const float*)d_in[9];
    const float* bs  = (const float*)d_in[10];
    const float* Wt  = (const float*)d_in[11];
    const float* bt  = (const float*)d_in[12];
    const int* perm  = (const int*)d_in[13];
    const int* ia    = (const int*)d_in[14];
    const int* ib    = (const int*)d_in[15];

    float* outz  = (float*)d_out;
    float* outld = outz + (size_t)BTOT * DIMV;

    int prep_tot = 6 * WPH_L + 6 * WPA_L;
    prep_w_kernel<<<(prep_tot + 255) / 256, 256>>>(W1, W2, W3, Ws, Wt);
    {
        size_t tot = 2 * (size_t)BTOT * 64;
        prep_a_kernel<<<(unsigned)((tot + 255) / 256), 256>>>(ctx, te);
    }

    cudaFuncSetAttribute(flow_fused_kernel,
                         cudaFuncAttributeMaxDynamicSharedMemorySize, SMEM_BYTES);
    dim3 grid(BTOT / MTILE), blk(NTHR);
    flow_fused_kernel<<<grid, blk, SMEM_BYTES>>>(
        x, outz, outld, b1, b2, b3, bs, bt, perm, ia, ib);
    (void)in_sizes; (void)n_in; (void)out_size;
}

// round 16
// speedup vs baseline: 1.2290x; 1.2290x over previous
#include <cuda_runtime.h>
#include <cuda_fp16.h>
#include <cstdint>

#define L_LAYERS 6
#define DIMV     40
#define HV       128
#define ADIMV    20
#define BTOT     131072
#define MTILE    64
#define NTHR     256
#define ZASTR    28

// fp16 packed weight segments per layer (uint32 words)
#define OC  0         // W1 ctx rows 20..147 : 8 ks16 x 8 ntp x 32 x 4
#define OT  8192      // W1 te  rows 148..275
#define O2  16384     // W2
#define O3  24576     // W3
#define O4  32768     // [Ws|Wt|0] : 8 ks16 x 6 nt x 32 x 2
#define WPH_L 35840
// tf32 za weights per layer (floats): 3 ks8 x 8 ntp x 32 x 4
#define WPA_L 3072

__device__ unsigned g_wph[6 * WPH_L];
__device__ float    g_wpa[6 * WPA_L];
__device__ unsigned g_apk[2 * (size_t)BTOT * 64];   // ctx|te fp16 A-frag order

// smem word offsets (double-buffered h)
#define SM_HF0  0                 // h frag buf0: 4096 words
#define SM_HF1  4096              // h frag buf1: 4096 words
#define SM_ST   8192              // st 64x41 fp32 = 2624
#define SM_Z    10816             // z 64x40 = 2560
#define SM_ZA   13376             // za 64x28 = 1792
#define SM_ZB   15168             // zb 64x20 = 1280
#define SM_IDX  16448             // 4 x 120 ints
#define SM_WORDS 16928
#define SMEM_BYTES (SM_WORDS * 4)

__device__ __forceinline__ unsigned f2tf(float x) {
    unsigned r;
    asm("cvt.rna.tf32.f32 %0, %1;" : "=r"(r) : "f"(x));
    return r;
}
__device__ __forceinline__ unsigned h2pack(float a, float b) {
    __half2 h = __floats2half2_rn(a, b);
    return *reinterpret_cast<unsigned*>(&h);
}
__device__ __forceinline__ void mma8(float c[4], const unsigned a[4], const unsigned b[2]) {
    asm volatile(
        "mma.sync.aligned.m16n8k8.row.col.f32.tf32.tf32.f32 "
        "{%0,%1,%2,%3}, {%4,%5,%6,%7}, {%8,%9}, {%0,%1,%2,%3};\n"
        : "+f"(c[0]), "+f"(c[1]), "+f"(c[2]), "+f"(c[3])
        : "r"(a[0]), "r"(a[1]), "r"(a[2]), "r"(a[3]), "r"(b[0]), "r"(b[1]));
}
__device__ __forceinline__ void mma16(float c[4], const unsigned a[4], unsigned b0, unsigned b1) {
    asm volatile(
        "mma.sync.aligned.m16n8k16.row.col.f32.f16.f16.f32 "
        "{%0,%1,%2,%3}, {%4,%5,%6,%7}, {%8,%9}, {%0,%1,%2,%3};\n"
        : "+f"(c[0]), "+f"(c[1]), "+f"(c[2]), "+f"(c[3])
        : "r"(a[0]), "r"(a[1]), "r"(a[2]), "r"(a[3]), "r"(b0), "r"(b1));
}
__device__ __forceinline__ float silu(float v) {
    return __fdividef(v, 1.0f + __expf(-v));
}

// ---------------------------------------------------------------------------
// prep: fp16 weights (frag order) + tf32 za weights   (identical to R10)
// ---------------------------------------------------------------------------
__global__ void prep_w_kernel(const float* __restrict__ W1, const float* __restrict__ W2,
                              const float* __restrict__ W3, const float* __restrict__ Ws,
                              const float* __restrict__ Wt) {
    int i = blockIdx.x * blockDim.x + threadIdx.x;
    const int FTOT = 6 * WPH_L;
    if (i < FTOT) {
        int layer = i / WPH_L;
        int w = i - layer * WPH_L;
        if (w < O4) {
            int seg = w / 8192;                 // 0:ctx 1:te 2:W2 3:W3
            int idx = w - seg * 8192;
            int comp = idx & 3, lane = (idx >> 2) & 31;
            int ntp = (idx >> 7) & 7, ks = idx >> 10;
            int g = lane >> 2, t4 = lane & 3;
            int col = (ntp * 2 + (comp >> 1)) * 8 + g;
            int k0 = ks * 16 + (comp & 1) * 8 + 2 * t4;
            float v0, v1;
            if (seg == 0) {
                const float* wsrc = W1 + (size_t)layer * 276 * HV;
                v0 = wsrc[(ADIMV + k0) * HV + col]; v1 = wsrc[(ADIMV + k0 + 1) * HV + col];
            } else if (seg == 1) {
                const float* wsrc = W1 + (size_t)layer * 276 * HV;
                v0 = wsrc[(ADIMV + 128 + k0) * HV + col]; v1 = wsrc[(ADIMV + 128 + k0 + 1) * HV + col];
            } else if (seg == 2) {
                const float* wsrc = W2 + (size_t)layer * HV * HV;
                v0 = wsrc[k0 * HV + col]; v1 = wsrc[(k0 + 1) * HV + col];
            } else {
                const float* wsrc = W3 + (size_t)layer * HV * HV;
                v0 = wsrc[k0 * HV + col]; v1 = wsrc[(k0 + 1) * HV + col];
            }
            g_wph[i] = h2pack(v0, v1);
        } else {
            int idx = w - O4;
            int comp = idx & 1, lane = (idx >> 1) & 31;
            int rest = idx >> 6;
            int nt = rest % 6, ks = rest / 6;
            int g = lane >> 2, t4 = lane & 3;
            int col = nt * 8 + g;
            int k0 = ks * 16 + comp * 8 + 2 * t4;
            float v0 = 0.0f, v1 = 0.0f;
            if (col < ADIMV) {
                const float* wsrc = Ws + (size_t)layer * HV * ADIMV;
                v0 = wsrc[k0 * ADIMV + col]; v1 = wsrc[(k0 + 1) * ADIMV + col];
            } else if (col < DIMV) {
                const float* wsrc = Wt + (size_t)layer * HV * ADIMV;
                v0 = wsrc[k0 * ADIMV + col - ADIMV]; v1 = wsrc[(k0 + 1) * ADIMV + col - ADIMV];
            }
            g_wph[i] = h2pack(v0, v1);
        }
        return;
    }
    int j = i - FTOT;
    if (j >= 6 * WPA_L) return;
    int layer = j / WPA_L;
    int idx = j - layer * WPA_L;
    int comp = idx & 3, lane = (idx >> 2) & 31;
    int blk = idx >> 7, ntp = blk & 7, ks = blk >> 3;
    int g = lane >> 2, t4 = lane & 3;
    int row = ks * 8 + t4 + 4 * (comp & 1);
    int col = (ntp * 2 + (comp >> 1)) * 8 + g;
    float v = (row < ADIMV) ? W1[(size_t)layer * 276 * HV + row * HV + col] : 0.0f;
    g_wpa[j] = __uint_as_float(f2tf(v));
}

// ctx/te -> fp16 A-frag order (identical to R10)
__global__ void prep_a_kernel(const float* __restrict__ ctx, const float* __restrict__ te) {
    size_t i = (size_t)blockIdx.x * blockDim.x + threadIdx.x;
    const size_t seg_sz = (size_t)BTOT * 64;
    if (i >= 2 * seg_sz) return;
    int seg = (int)(i / seg_sz);
    size_t idx = i - (size_t)seg * seg_sz;
    int comp = (int)(idx & 3);
    int lane = (int)((idx >> 2) & 31);
    int kb = (int)((idx >> 7) & 7);
    size_t rb16 = idx >> 10;
    int g = lane >> 2, t4 = lane & 3;
    size_t row = rb16 * 16 + g + 8 * (comp & 1);
    int kcol = kb * 16 + 8 * (comp >> 1) + 2 * t4;
    const float* src = seg ? te : ctx;
    g_apk[i] = h2pack(src[row * HV + kcol], src[row * HV + kcol + 1]);
}

// ---------------------------------------------------------------------------
// fp16 GEMM pieces: warp tile 16x64, 4wm x 2wn over 64x128 (identical to R10)
// ---------------------------------------------------------------------------
__device__ __forceinline__ void gemm_h128(float acc[8][4], const unsigned* __restrict__ hw,
                                          const unsigned* __restrict__ Wp,
                                          int wm, int wn, int lane) {
    const uint4* bp = reinterpret_cast<const uint4*>(Wp);
#pragma unroll
    for (int ks = 0; ks < 8; ks++) {
        unsigned a[4];
        const unsigned* ab = hw + ((wm * 8 + ks) * 4) * 32 + lane;
        a[0] = ab[0]; a[1] = ab[32]; a[2] = ab[64]; a[3] = ab[96];
        const uint4* bb = bp + (ks * 8 + wn * 4) * 32 + lane;
#pragma unroll
        for (int ntp = 0; ntp < 4; ntp++) {
            uint4 bv = __ldg(bb + ntp * 32);
            mma16(acc[2 * ntp], a, bv.x, bv.y);
            mma16(acc[2 * ntp + 1], a, bv.z, bv.w);
        }
    }
}

__device__ __forceinline__ void gemm_pk128(float acc[8][4], const unsigned* __restrict__ Apk,
                                           const unsigned* __restrict__ Wp, int rb16,
                                           int wn, int lane) {
    const uint4* ap = reinterpret_cast<const uint4*>(Apk);
    const uint4* bp = reinterpret_cast<const uint4*>(Wp);
#pragma unroll
    for (int ks = 0; ks < 8; ks++) {
        uint4 av = __ldg(ap + ((size_t)rb16 * 8 + ks) * 32 + lane);
        unsigned a[4] = {av.x, av.y, av.z, av.w};
        const uint4* bb = bp + (ks * 8 + wn * 4) * 32 + lane;
#pragma unroll
        for (int ntp = 0; ntp < 4; ntp++) {
            uint4 bv = __ldg(bb + ntp * 32);
            mma16(acc[2 * ntp], a, bv.x, bv.y);
            mma16(acc[2 * ntp + 1], a, bv.z, bv.w);
        }
    }
}

// epilogue: silu+bias -> h frag store (own lane, conflict-free)
__device__ __forceinline__ void epi_silu_h(float acc[8][4], const float* __restrict__ bias,
                                           unsigned* __restrict__ hw,
                                           int wm, int wn, int lane, int t4) {
#pragma unroll
    for (int nt = 0; nt < 8; nt++) {
        int c0 = wn * 64 + nt * 8 + t4 * 2;
        float bb0 = __ldg(bias + c0);
        float bb1 = __ldg(bias + c0 + 1);
        float v0 = silu(acc[nt][0] + bb0);
        float v1 = silu(acc[nt][1] + bb1);
        float v2 = silu(acc[nt][2] + bb0);
        float v3 = silu(acc[nt][3] + bb1);
        int kb = wn * 4 + (nt >> 1);
        int cb = (nt & 1) * 2;
        hw[((wm * 8 + kb) * 4 + cb) * 32 + lane]     = h2pack(v0, v1);
        hw[((wm * 8 + kb) * 4 + cb + 1) * 32 + lane] = h2pack(v2, v3);
    }
}

__device__ __forceinline__ void zacc8(float acc[8][4]) {
#pragma unroll
    for (int nt = 0; nt < 8; nt++)
#pragma unroll
        for (int e = 0; e < 4; e++) acc[nt][e] = 0.0f;
}

// ---------------------------------------------------------------------------
__global__ void __launch_bounds__(NTHR)
flow_fused_kernel(const float* __restrict__ xin, float* __restrict__ zfinal,
                  float* __restrict__ ldfinal,
                  const float* __restrict__ b1, const float* __restrict__ b2,
                  const float* __restrict__ b3, const float* __restrict__ bsw,
                  const float* __restrict__ btw,
                  const int* __restrict__ perm, const int* __restrict__ idxa,
                  const int* __restrict__ idxb) {
    extern __shared__ unsigned smw[];
    unsigned* hw0 = smw + SM_HF0;
    unsigned* hw1 = smw + SM_HF1;
    float* st_s   = (float*)(smw + SM_ST);
    float* z_s    = (float*)(smw + SM_Z);
    float* za_s   = (float*)(smw + SM_ZA);
    float* zb_s   = (float*)(smw + SM_ZB);
    int* sga_all  = (int*)(smw + SM_IDX);
    int* sgb_all  = sga_all + 120;
    int* sia_all  = sgb_all + 120;
    int* sib_all  = sia_all + 120;

    const int tid = threadIdx.x;
    const int warp = tid >> 5, lane = tid & 31;
    const int g = lane >> 2, t4 = lane & 3;
    const int wm = warp >> 1, wn = warp & 1;
    const int rb = blockIdx.x * MTILE;
    const int rb16 = (rb >> 4) + wm;

    if (tid < 120) {
        int l = tid / 20, k = tid - l * 20;
        int v = idxa[l * ADIMV + k];
        sia_all[tid] = v;
        sga_all[tid] = perm[l * DIMV + v];
    } else if (tid < 240) {
        int u = tid - 120;
        int l = u / 20, k = u - l * 20;
        int v = idxb[l * ADIMV + k];
        sib_all[u] = v;
        sgb_all[u] = perm[l * DIMV + v];
    }
    for (int i = tid; i < MTILE * DIMV; i += NTHR)
        z_s[i] = xin[(size_t)rb * DIMV + i];

    float ldacc = 0.0f;

    for (int layer = 0; layer < L_LAYERS; layer++) {
        const unsigned* wl = g_wph + layer * WPH_L;
        const float* wla = g_wpa + layer * WPA_L;
        const int* sga = sga_all + layer * 20;
        const int* sgb = sgb_all + layer * 20;
        const int* sia = sia_all + layer * 20;
        const int* sib = sib_all + layer * 20;

        __syncthreads();
        for (int i = tid; i < MTILE * ADIMV; i += NTHR) {
            int r = i / ADIMV, k = i - r * ADIMV;
            za_s[r * ZASTR + k] = z_s[r * DIMV + sga[k]];
            zb_s[r * ADIMV + k] = z_s[r * DIMV + sgb[k]];
        }
        for (int i = tid; i < MTILE * 4; i += NTHR) {
            int r = i >> 2;
            za_s[r * ZASTR + ADIMV + (i & 3)] = 0.0f;
        }
        __syncthreads();

        float acc[8][4];
        zacc8(acc);

        // GEMM1 seg z_a: tf32 k8 x 3
        {
            const float4* bp = reinterpret_cast<const float4*>(wla);
#pragma unroll
            for (int ks = 0; ks < 3; ks++) {
                const float* ar = za_s + (wm * 16 + g) * ZASTR + ks * 8 + t4;
                unsigned a[4];
                a[0] = f2tf(ar[0]);
                a[1] = f2tf(ar[8 * ZASTR]);
                a[2] = f2tf(ar[4]);
                a[3] = f2tf(ar[8 * ZASTR + 4]);
                const float4* bb = bp + (ks * 8 + wn * 4) * 32 + lane;
#pragma unroll
                for (int ntp = 0; ntp < 4; ntp++) {
                    float4 bv = __ldg(bb + ntp * 32);
                    unsigned b0[2] = {__float_as_uint(bv.x), __float_as_uint(bv.y)};
                    unsigned b1[2] = {__float_as_uint(bv.z), __float_as_uint(bv.w)};
                    mma8(acc[2 * ntp], a, b0);
                    mma8(acc[2 * ntp + 1], a, b1);
                }
            }
        }
        // GEMM1 ctx / te (fp16, prepacked gmem A) -> epi writes hw0
        gemm_pk128(acc, g_apk, wl + OC, rb16, wn, lane);
        gemm_pk128(acc, g_apk + (size_t)BTOT * 64, wl + OT, rb16, wn, lane);
        epi_silu_h(acc, b1 + layer * HV, hw0, wm, wn, lane, t4);
        __syncthreads();

        // GEMM2 reads hw0 -> epi writes hw1 (no WAR barrier needed)
        zacc8(acc);
        gemm_h128(acc, hw0, wl + O2, wm, wn, lane);
        epi_silu_h(acc, b2 + layer * HV, hw1, wm, wn, lane, t4);
        __syncthreads();

        // GEMM3 reads hw1 -> epi writes hw0
        zacc8(acc);
        gemm_h128(acc, hw1, wl + O3, wm, wn, lane);
        epi_silu_h(acc, b3 + layer * HV, hw0, wm, wn, lane, t4);
        __syncthreads();

        // GEMM4 reads hw0: N=48, warp tile 16x24
        float a4[3][4];
#pragma unroll
        for (int nt = 0; nt < 3; nt++)
#pragma unroll
            for (int e = 0; e < 4; e++) a4[nt][e] = 0.0f;
        {
            const uint2* bp4 = reinterpret_cast<const uint2*>(wl + O4);
#pragma unroll
            for (int ks = 0; ks < 8; ks++) {
                unsigned a[4];
                const unsigned* ab = hw0 + ((wm * 8 + ks) * 4) * 32 + lane;
                a[0] = ab[0]; a[1] = ab[32]; a[2] = ab[64]; a[3] = ab[96];
#pragma unroll
                for (int nt = 0; nt < 3; nt++) {
                    uint2 bv = __ldg(bp4 + (ks * 6 + wn * 3 + nt) * 32 + lane);
                    mma16(a4[nt], a, bv.x, bv.y);
                }
            }
        }
        // epilogue4 -> st (fp32, separate buffer: no WAR barrier)
        {
            const float* bsl = bsw + layer * ADIMV;
            const float* btl = btw + layer * ADIMV;
#pragma unroll
            for (int nt = 0; nt < 3; nt++)
#pragma unroll
                for (int e = 0; e < 4; e++) {
                    int row = wm * 16 + g + ((e >= 2) ? 8 : 0);
                    int col = wn * 24 + nt * 8 + t4 * 2 + (e & 1);
                    if (col < DIMV) {
                        float v = a4[nt][e];
                        if (col < ADIMV) {
                            v += __ldg(bsl + col);
                            v = fminf(fmaxf(v, -2.0f), 2.0f);
                        } else {
                            v += __ldg(btl + col - ADIMV);
                        }
                        st_s[row * 41 + col] = v;
                    }
                }
        }
        __syncthreads();

        // coupling: 4 threads/row
        {
            int r = tid >> 2, q = tid & 3;
            const float* strow = st_s + r * 41;
            float ssum = 0.0f;
#pragma unroll
            for (int j = 0; j < 5; j++) {
                int k = q * 5 + j;
                float s = strow[k];
                float t = strow[ADIMV + k];
                ssum += s;
                float yb = zb_s[r * ADIMV + k] * __expf(s) + t;
                z_s[r * DIMV + sib[k]] = yb;
                z_s[r * DIMV + sia[k]] = za_s[r * ZASTR + k];
            }
            ssum += __shfl_xor_sync(0xffffffffu, ssum, 1);
            ssum += __shfl_xor_sync(0xffffffffu, ssum, 2);
            ldacc += ssum;
        }
        (void)wla;
    }

    __syncthreads();
    for (int i = tid; i < MTILE * DIMV; i += NTHR)
        zfinal[(size_t)rb * DIMV + i] = z_s[i];
    if ((tid & 3) == 0)
        ldfinal[(size_t)rb + (tid >> 2)] = ldacc;
}

extern "C" void kernel_launch(void* const* d_in, const int* in_sizes, int n_in,
                              void* d_out, int out_size) {
    const float* x   = (const float*)d_in[0];
    const float* ctx = (const float*)d_in[1];
    const float* te  = (const float*)d_in[2];
    const float* W1  = (const float*)d_in[3];
    const float* b1  = (const float*)d_in[4];
    const float* W2  = (const float*)d_in[5];
    const float* b2  = (const float*)d_in[6];
    const float* W3  = (const float*)d_in[7];
    const float* b3  = (const float*)d_in[8];
    const float* Ws  = (const float*)d_in[9];
    const float* bs  = (const float*)d_in[10];
    const float* Wt  = (const float*)d_in[11];
    const float* bt  = (const float*)d_in[12];
    const int* perm  = (const int*)d_in[13];
    const int* ia    = (const int*)d_in[14];
    const int* ib    = (const int*)d_in[15];

    float* outz  = (float*)d_out;
    float* outld = outz + (size_t)BTOT * DIMV;

    int prep_tot = 6 * WPH_L + 6 * WPA_L;
    prep_w_kernel<<<(prep_tot + 255) / 256, 256>>>(W1, W2, W3, Ws, Wt);
    {
        size_t tot = 2 * (size_t)BTOT * 64;
        prep_a_kernel<<<(unsigned)((tot + 255) / 256), 256>>>(ctx, te);
    }

    cudaFuncSetAttribute(flow_fused_kernel,
                         cudaFuncAttributeMaxDynamicSharedMemorySize, SMEM_BYTES);
    dim3 grid(BTOT / MTILE), blk(NTHR);
    flow_fused_kernel<<<grid, blk, SMEM_BYTES>>>(
        x, outz, outld, b1, b2, b3, bs, bt, perm, ia, ib);
    (void)in_sizes; (void)n_in; (void)out_size;
}